// round 1
// baseline (speedup 1.0000x reference)
#include <cuda_runtime.h>
#include <math.h>

// ---------------- problem constants ----------------
constexpr int LAY = 8;
constexpr int NH  = 16;
constexpr int EMB = 1024;
constexpr int VOC = 32000;
constexpr int SEQ = 1024;
constexpr int BSZ = 2;
constexpr int HSD = 64;        // head size
constexpr int DFF = 4096;
constexpr int MROWS = BSZ * SEQ;   // 2048

// ---------------- scratch (device globals; no cudaMalloc allowed) ----------------
__device__ float g_x [MROWS * EMB];   // residual stream
__device__ float g_h [MROWS * EMB];   // layernorm output
__device__ float g_q [MROWS * EMB];
__device__ float g_k [MROWS * EMB];
__device__ float g_v [MROWS * EMB];
__device__ float g_o [MROWS * EMB];
__device__ float g_ff[MROWS * DFF];   // MLP hidden

// ---------------- embedding ----------------
__global__ void embed_kernel(float* __restrict__ x, const int* __restrict__ idx,
                             const float* __restrict__ tok, const float* __restrict__ pos)
{
    int i = blockIdx.x * blockDim.x + threadIdx.x;    // over MROWS*EMB
    int e  = i & (EMB - 1);
    int bt = i >> 10;                // /EMB
    int t  = bt & (SEQ - 1);
    x[i] = tok[(size_t)idx[bt] * EMB + e] + pos[(size_t)t * EMB + e];
}

// ---------------- layernorm (one block per row, 256 threads, E=1024) ----------------
__global__ __launch_bounds__(256) void ln_kernel(float* __restrict__ out,
                                                 const float* __restrict__ in,
                                                 const float* __restrict__ g,
                                                 const float* __restrict__ b)
{
    const int row = blockIdx.x;
    const float* xr = in + (size_t)row * EMB;
    float v[4];
    float s = 0.f;
    #pragma unroll
    for (int i = 0; i < 4; i++) { v[i] = xr[threadIdx.x + i * 256]; s += v[i]; }

    __shared__ float red[8];
    __shared__ float mean_s, rstd_s;

    #pragma unroll
    for (int o = 16; o; o >>= 1) s += __shfl_xor_sync(0xffffffffu, s, o);
    if ((threadIdx.x & 31) == 0) red[threadIdx.x >> 5] = s;
    __syncthreads();
    if (threadIdx.x == 0) {
        float t = 0.f;
        #pragma unroll
        for (int i = 0; i < 8; i++) t += red[i];
        mean_s = t * (1.f / EMB);
    }
    __syncthreads();
    const float m = mean_s;

    float ss = 0.f;
    #pragma unroll
    for (int i = 0; i < 4; i++) { float d = v[i] - m; ss += d * d; }
    #pragma unroll
    for (int o = 16; o; o >>= 1) ss += __shfl_xor_sync(0xffffffffu, ss, o);
    if ((threadIdx.x & 31) == 0) red[threadIdx.x >> 5] = ss;
    __syncthreads();
    if (threadIdx.x == 0) {
        float t = 0.f;
        #pragma unroll
        for (int i = 0; i < 8; i++) t += red[i];
        rstd_s = rsqrtf(t * (1.f / EMB) + 1e-5f);
    }
    __syncthreads();
    const float r = rstd_s;

    #pragma unroll
    for (int i = 0; i < 4; i++) {
        int col = threadIdx.x + i * 256;
        out[(size_t)row * EMB + col] = (v[i] - m) * r * g[col] + b[col];
    }
}

// ---------------- SGEMM: C[M,N] = A[M,K] @ B(+T) [+bias][+res][relu] ----------------
// BM=BN=128, BK=8, 256 threads, 8x8 microtile. All dims are multiples (no bounds checks).
template<bool BTRANS, bool BIAS, bool RELU, bool RES>
__global__ __launch_bounds__(256) void gemm_kernel(
    const float* __restrict__ A, const float* __restrict__ Bm,
    const float* __restrict__ bias, const float* __restrict__ res,
    float* __restrict__ C, int M, int N, int K)
{
    __shared__ float As[8][128];
    __shared__ float Bs[8][128];
    const int tid = threadIdx.x;
    const int bm0 = blockIdx.y * 128;
    const int bn0 = blockIdx.x * 128;
    const int ty = tid >> 4;     // 0..15
    const int tx = tid & 15;     // 0..15

    const int arow = tid >> 1;          // 0..127
    const int ak4  = (tid & 1) * 4;     // 0 or 4
    const float* Ap = A + (size_t)(bm0 + arow) * K + ak4;

    const float* Bp;
    if (BTRANS) {
        Bp = Bm + (size_t)(bn0 + arow) * K + ak4;     // Bm is [N,K]
    } else {
        Bp = Bm + (size_t)(tid >> 5) * N + bn0 + (tid & 31) * 4;  // [K,N]
    }

    float acc[8][8];
    #pragma unroll
    for (int i = 0; i < 8; i++)
        #pragma unroll
        for (int j = 0; j < 8; j++) acc[i][j] = 0.f;

    for (int k0 = 0; k0 < K; k0 += 8) {
        float4 av = *reinterpret_cast<const float4*>(Ap + k0);
        As[ak4 + 0][arow] = av.x;
        As[ak4 + 1][arow] = av.y;
        As[ak4 + 2][arow] = av.z;
        As[ak4 + 3][arow] = av.w;
        if (BTRANS) {
            float4 bv = *reinterpret_cast<const float4*>(Bp + k0);
            Bs[ak4 + 0][arow] = bv.x;
            Bs[ak4 + 1][arow] = bv.y;
            Bs[ak4 + 2][arow] = bv.z;
            Bs[ak4 + 3][arow] = bv.w;
        } else {
            float4 bv = *reinterpret_cast<const float4*>(Bp + (size_t)k0 * N);
            *reinterpret_cast<float4*>(&Bs[tid >> 5][(tid & 31) * 4]) = bv;
        }
        __syncthreads();
        #pragma unroll
        for (int kk = 0; kk < 8; kk++) {
            float a[8], b[8];
            *reinterpret_cast<float4*>(&a[0]) = *reinterpret_cast<const float4*>(&As[kk][ty * 8]);
            *reinterpret_cast<float4*>(&a[4]) = *reinterpret_cast<const float4*>(&As[kk][ty * 8 + 4]);
            *reinterpret_cast<float4*>(&b[0]) = *reinterpret_cast<const float4*>(&Bs[kk][tx * 8]);
            *reinterpret_cast<float4*>(&b[4]) = *reinterpret_cast<const float4*>(&Bs[kk][tx * 8 + 4]);
            #pragma unroll
            for (int i = 0; i < 8; i++)
                #pragma unroll
                for (int j = 0; j < 8; j++)
                    acc[i][j] += a[i] * b[j];
        }
        __syncthreads();
    }

    #pragma unroll
    for (int i = 0; i < 8; i++) {
        const int row = bm0 + ty * 8 + i;
        #pragma unroll
        for (int jv = 0; jv < 2; jv++) {
            const int col = bn0 + tx * 8 + jv * 4;
            float4 r;
            r.x = acc[i][jv * 4 + 0]; r.y = acc[i][jv * 4 + 1];
            r.z = acc[i][jv * 4 + 2]; r.w = acc[i][jv * 4 + 3];
            if (BIAS) {
                float4 bv = *reinterpret_cast<const float4*>(bias + col);
                r.x += bv.x; r.y += bv.y; r.z += bv.z; r.w += bv.w;
            }
            if (RES) {
                float4 rv = *reinterpret_cast<const float4*>(res + (size_t)row * N + col);
                r.x += rv.x; r.y += rv.y; r.z += rv.z; r.w += rv.w;
            }
            if (RELU) {
                r.x = fmaxf(r.x, 0.f); r.y = fmaxf(r.y, 0.f);
                r.z = fmaxf(r.z, 0.f); r.w = fmaxf(r.w, 0.f);
            }
            *reinterpret_cast<float4*>(C + (size_t)row * N + col) = r;
        }
    }
}

// ---------------- flash attention (fp32, causal), 64-query tiles ----------------
// Q,K,V,O stored as [B,T,E] with E = h*64+d. grid = (SEQ/64, BSZ*NH), 256 threads.
constexpr int QP = 68;  // Qs pitch (float4-aligned, conflict-benign)
constexpr int KP = 65;  // Ks (transposed [d][key]) pitch (scalar stores)
constexpr int VP = 68;
constexpr int PP = 68;
constexpr int ATTN_SMEM = (64 * QP + 64 * KP + 64 * VP + 64 * PP) * 4;   // 68,864 B

__global__ __launch_bounds__(256) void attn_kernel(const float* __restrict__ Q,
                                                   const float* __restrict__ Kc,
                                                   const float* __restrict__ Vc,
                                                   float* __restrict__ O)
{
    extern __shared__ float sm[];
    float* Qs = sm;                  // [64][QP]  (q-row major)
    float* Ks = Qs + 64 * QP;        // [64][KP]  TRANSPOSED: Ks[d*KP + key]
    float* Vs = Ks + 64 * KP;        // [64][VP]  (key-row major)
    float* Ps = Vs + 64 * VP;        // [64][PP]  probs

    const int qt  = blockIdx.x;
    const int bh  = blockIdx.y;
    const int b   = bh >> 4;
    const int h   = bh & 15;
    const int tid = threadIdx.x;
    const int ty  = tid >> 4;   // 0..15 -> query rows 4*ty..+3
    const int tx  = tid & 15;   // 0..15 -> cols 4*tx..+3

    const size_t baseQ = ((size_t)(b * SEQ + qt * 64)) * EMB + h * 64;

    #pragma unroll
    for (int r = 0; r < 4; r++) {
        int id = tid + r * 256;
        int row = id >> 4, c4 = id & 15;
        float4 qv = *reinterpret_cast<const float4*>(Q + baseQ + (size_t)row * EMB + c4 * 4);
        *reinterpret_cast<float4*>(&Qs[row * QP + c4 * 4]) = qv;
    }

    float m[4], l[4], oacc[4][4];
    #pragma unroll
    for (int i = 0; i < 4; i++) {
        m[i] = -1e30f; l[i] = 0.f;
        #pragma unroll
        for (int j = 0; j < 4; j++) oacc[i][j] = 0.f;
    }
    const float scale = 0.125f;   // HS^-0.5 = 1/8

    for (int jt = 0; jt <= qt; jt++) {
        __syncthreads();   // previous PV + Q load done before overwriting tiles
        const size_t baseK = ((size_t)(b * SEQ + jt * 64)) * EMB + h * 64;
        #pragma unroll
        for (int r = 0; r < 4; r++) {
            int id = tid + r * 256;
            int row = id >> 4, c4 = id & 15;
            float4 kv = *reinterpret_cast<const float4*>(Kc + baseK + (size_t)row * EMB + c4 * 4);
            Ks[(c4 * 4 + 0) * KP + row] = kv.x;
            Ks[(c4 * 4 + 1) * KP + row] = kv.y;
            Ks[(c4 * 4 + 2) * KP + row] = kv.z;
            Ks[(c4 * 4 + 3) * KP + row] = kv.w;
            float4 vv = *reinterpret_cast<const float4*>(Vc + baseK + (size_t)row * EMB + c4 * 4);
            *reinterpret_cast<float4*>(&Vs[row * VP + c4 * 4]) = vv;
        }
        __syncthreads();

        float s[4][4];
        #pragma unroll
        for (int i = 0; i < 4; i++)
            #pragma unroll
            for (int j = 0; j < 4; j++) s[i][j] = 0.f;

        #pragma unroll 8
        for (int d = 0; d < 64; d++) {
            float qa[4], kb[4];
            #pragma unroll
            for (int i = 0; i < 4; i++) qa[i] = Qs[(ty * 4 + i) * QP + d];
            #pragma unroll
            for (int j = 0; j < 4; j++) kb[j] = Ks[d * KP + tx * 4 + j];
            #pragma unroll
            for (int i = 0; i < 4; i++)
                #pragma unroll
                for (int j = 0; j < 4; j++) s[i][j] += qa[i] * kb[j];
        }

        const bool diag = (jt == qt);
        #pragma unroll
        for (int i = 0; i < 4; i++)
            #pragma unroll
            for (int j = 0; j < 4; j++) {
                s[i][j] *= scale;
                if (diag && (tx * 4 + j) > (ty * 4 + i)) s[i][j] = -1e30f;
            }

        #pragma unroll
        for (int i = 0; i < 4; i++) {
            float mx = fmaxf(fmaxf(s[i][0], s[i][1]), fmaxf(s[i][2], s[i][3]));
            #pragma unroll
            for (int o = 8; o; o >>= 1) mx = fmaxf(mx, __shfl_xor_sync(0xffffffffu, mx, o, 16));
            float mnew = fmaxf(m[i], mx);
            float alpha = __expf(m[i] - mnew);
            m[i] = mnew;
            float rs = 0.f;
            #pragma unroll
            for (int j = 0; j < 4; j++) {
                float p = __expf(s[i][j] - mnew);
                s[i][j] = p; rs += p;
            }
            #pragma unroll
            for (int o = 8; o; o >>= 1) rs += __shfl_xor_sync(0xffffffffu, rs, o, 16);
            l[i] = l[i] * alpha + rs;
            #pragma unroll
            for (int j = 0; j < 4; j++) oacc[i][j] *= alpha;
        }

        #pragma unroll
        for (int i = 0; i < 4; i++)
            #pragma unroll
            for (int j = 0; j < 4; j++)
                Ps[(ty * 4 + i) * PP + tx * 4 + j] = s[i][j];
        __syncthreads();

        #pragma unroll 8
        for (int kk = 0; kk < 64; kk++) {
            float pa[4], vb[4];
            #pragma unroll
            for (int i = 0; i < 4; i++) pa[i] = Ps[(ty * 4 + i) * PP + kk];
            #pragma unroll
            for (int j = 0; j < 4; j++) vb[j] = Vs[kk * VP + tx * 4 + j];
            #pragma unroll
            for (int i = 0; i < 4; i++)
                #pragma unroll
                for (int j = 0; j < 4; j++) oacc[i][j] += pa[i] * vb[j];
        }
    }

    #pragma unroll
    for (int i = 0; i < 4; i++) {
        float inv = 1.f / l[i];
        #pragma unroll
        for (int j = 0; j < 4; j++)
            O[baseQ + (size_t)(ty * 4 + i) * EMB + tx * 4 + j] = oacc[i][j] * inv;
    }
}

// ---------------- host orchestration ----------------
extern "C" void kernel_launch(void* const* d_in, const int* in_sizes, int n_in,
                              void* d_out, int out_size)
{
    const int*   idx  = (const int*)  d_in[0];
    const float* tok  = (const float*)d_in[1];
    const float* pos  = (const float*)d_in[2];
    const float* Wq   = (const float*)d_in[3];
    const float* Wk   = (const float*)d_in[4];
    const float* Wv   = (const float*)d_in[5];
    const float* Wo   = (const float*)d_in[6];
    const float* bo   = (const float*)d_in[7];
    const float* W1   = (const float*)d_in[8];
    const float* b1   = (const float*)d_in[9];
    const float* W2   = (const float*)d_in[10];
    const float* b2   = (const float*)d_in[11];
    const float* ln1g = (const float*)d_in[12];
    const float* ln1b = (const float*)d_in[13];
    const float* ln2g = (const float*)d_in[14];
    const float* ln2b = (const float*)d_in[15];
    const float* lnfg = (const float*)d_in[16];
    const float* lnfb = (const float*)d_in[17];
    const float* lmb  = (const float*)d_in[18];
    float* out = (float*)d_out;

    float *x, *h, *q, *k, *v, *o, *ff;
    cudaGetSymbolAddress((void**)&x,  g_x);
    cudaGetSymbolAddress((void**)&h,  g_h);
    cudaGetSymbolAddress((void**)&q,  g_q);
    cudaGetSymbolAddress((void**)&k,  g_k);
    cudaGetSymbolAddress((void**)&v,  g_v);
    cudaGetSymbolAddress((void**)&o,  g_o);
    cudaGetSymbolAddress((void**)&ff, g_ff);

    cudaFuncSetAttribute(attn_kernel, cudaFuncAttributeMaxDynamicSharedMemorySize, ATTN_SMEM);

    embed_kernel<<<(MROWS * EMB) / 256, 256>>>(x, idx, tok, pos);

    const dim3 g1024(EMB / 128, MROWS / 128);   // N=1024
    const dim3 g4096(DFF / 128, MROWS / 128);   // N=4096
    const dim3 gvoc (VOC / 128, MROWS / 128);   // N=32000

    for (int l = 0; l < LAY; l++) {
        const size_t wo = (size_t)l * EMB * EMB;
        ln_kernel<<<MROWS, 256>>>(h, x, ln1g + (size_t)l * EMB, ln1b + (size_t)l * EMB);
        gemm_kernel<false, false, false, false><<<g1024, 256>>>(h, Wq + wo, nullptr, nullptr, q, MROWS, EMB, EMB);
        gemm_kernel<false, false, false, false><<<g1024, 256>>>(h, Wk + wo, nullptr, nullptr, k, MROWS, EMB, EMB);
        gemm_kernel<false, false, false, false><<<g1024, 256>>>(h, Wv + wo, nullptr, nullptr, v, MROWS, EMB, EMB);
        attn_kernel<<<dim3(SEQ / 64, BSZ * NH), 256, ATTN_SMEM>>>(q, k, v, o);
        gemm_kernel<false, true, false, true><<<g1024, 256>>>(o, Wo + wo, bo + (size_t)l * EMB, x, x, MROWS, EMB, EMB);
        ln_kernel<<<MROWS, 256>>>(h, x, ln2g + (size_t)l * EMB, ln2b + (size_t)l * EMB);
        gemm_kernel<false, true, true, false><<<g4096, 256>>>(h, W1 + (size_t)l * EMB * DFF, b1 + (size_t)l * DFF, nullptr, ff, MROWS, DFF, EMB);
        gemm_kernel<false, true, false, true><<<g1024, 256>>>(ff, W2 + (size_t)l * DFF * EMB, b2 + (size_t)l * EMB, x, x, MROWS, EMB, DFF);
    }

    ln_kernel<<<MROWS, 256>>>(h, x, lnfg, lnfb);
    // logits = h @ tok^T + lm_b   (tok is [V,E] -> B transposed)
    gemm_kernel<true, true, false, false><<<gvoc, 256>>>(h, tok, lmb, nullptr, out, MROWS, VOC, EMB);
}